// round 17
// baseline (speedup 1.0000x reference)
#include <cuda_runtime.h>
#include <cuda_fp16.h>
#include <cstdint>

#define BB 32
#define DD 640
#define MM 1024
#define TRI (DD*(DD+1)/2)
#define TEMPR (1.0f/(2.0f*DD*MM))
#define EPSV 1e-5f

#define NBL 10                /* 640/64 col blocks */
#define NU  30                /* 5 diag singles + 25 pairs per batch */
#define KC 32                 /* f16 K per chunk; hi|lo packed -> 128B/row */
#define NCH (MM/KC)           /* 32 chunks */

// ---- device scratch (no runtime allocation) ----
__device__ __align__(256) __half g_hl[(size_t)BB*DD*2048];         // 83.9 MB
__device__ __align__(256) float g_dcov[(size_t)BB*DD*DD];          // upper tiles only
__device__ float g_diag[BB*DD];
__device__ float g_rspart[(size_t)BB*NBL*DD];
__device__ float g_rowsum[BB*DD];   // pre-scaled by 1/D
__device__ float g_tot[BB];         // pre-scaled by 1/D^2

// ---------------- baseline-PTX helpers ----------------
__device__ __forceinline__ uint32_t smem_u32(const void* p) {
    uint32_t a;
    asm("{ .reg .u64 t; cvta.to.shared.u64 t, %1; cvt.u32.u64 %0, t; }" : "=r"(a) : "l"(p));
    return a;
}
#define SW128(o) ((o) ^ (((o) >> 3) & 0x70))
#define SW64(o)  ((o) ^ (((o) >> 3) & 0x30))

#define CVT2F16(d, hi, lo) \
    asm("cvt.rn.f16x2.f32 %0, %1, %2;" : "=r"(d) : "f"(hi), "f"(lo))

#define CP_ASYNC16(dst, src) \
    asm volatile("cp.async.cg.shared.global [%0], [%1], 16;" :: "r"(dst), "l"(src) : "memory")
#define CP_COMMIT() asm volatile("cp.async.commit_group;" ::: "memory")
#define CP_WAIT0()  asm volatile("cp.async.wait_group 0;" ::: "memory")

#define LDSM4(r, addr) \
    asm volatile("ldmatrix.sync.aligned.m8n8.x4.shared.b16 {%0,%1,%2,%3}, [%4];" \
                 : "=r"((r)[0]), "=r"((r)[1]), "=r"((r)[2]), "=r"((r)[3]) : "r"(addr))

#define MMA_F16(c, a, b0, b1) \
    asm volatile("mma.sync.aligned.m16n8k16.row.col.f32.f16.f16.f32 " \
                 "{%0,%1,%2,%3}, {%4,%5,%6,%7}, {%8,%9}, {%0,%1,%2,%3};" \
                 : "+f"((c)[0]), "+f"((c)[1]), "+f"((c)[2]), "+f"((c)[3]) \
                 : "r"((a)[0]), "r"((a)[1]), "r"((a)[2]), "r"((a)[3]), "r"(b0), "r"(b1))

// ---------------------------------------------------------------------------
// Kernel 1: fp32 -> packed (hi|lo) f16 + diag row-norms. One warp per row.
// ---------------------------------------------------------------------------
__global__ void conv_diag_kernel(const float* __restrict__ x) {
    int w = (blockIdx.x * blockDim.x + threadIdx.x) >> 5;
    int lane = threadIdx.x & 31;
    if (w >= BB * DD) return;
    const float4* row = reinterpret_cast<const float4*>(x + (size_t)w * MM);
    __half* pr = g_hl + (size_t)w * 2048;
    float s = 0.f;
    #pragma unroll
    for (int m4 = lane; m4 < MM / 4; m4 += 32) {
        float4 v = row[m4];
        s += v.x*v.x + v.y*v.y + v.z*v.z + v.w*v.w;
        uint32_t hA, hB;
        CVT2F16(hA, v.y, v.x);
        CVT2F16(hB, v.w, v.z);
        float2 fA = __half22float2(*reinterpret_cast<__half2*>(&hA));
        float2 fB = __half22float2(*reinterpret_cast<__half2*>(&hB));
        uint32_t lA, lB;
        CVT2F16(lA, v.y - fA.y, v.x - fA.x);
        CVT2F16(lB, v.w - fB.y, v.z - fB.x);
        int col0 = m4 * 4;
        int kc = col0 >> 5, wi = col0 & 31;
        uint2 hp; hp.x = hA; hp.y = hB;
        uint2 lp; lp.x = lA; lp.y = lB;
        *reinterpret_cast<uint2*>(pr + kc * 64 + wi)      = hp;
        *reinterpret_cast<uint2*>(pr + kc * 64 + 32 + wi) = lp;
    }
    #pragma unroll
    for (int o = 16; o > 0; o >>= 1) s += __shfl_down_sync(0xffffffffu, s, o);
    if (lane == 0) g_diag[w] = s;
}

// ---------------------------------------------------------------------------
// Kernel 2: Gram f16 hi/lo 2-pass. Work units per batch: 5 diag 64x64
// singles + 25 paired 128x64 tiles (A strip 128 rows hi-only shared).
// smem/stage: A(hi) 8KB @0 (SW64), B(hi|lo) 8KB @8192 (SW128); 2 stages.
// ---------------------------------------------------------------------------
#define STAGE_BYTES 16384
#define SMEM_BYTES  32768

__device__ __forceinline__ void load_A(const __half* src, uint32_t dst,
                                       int kc, int tid, int rows) {
    for (int it = 0; it < rows / 32; it++) {
        int idx = it * 128 + tid;
        int row = idx >> 2, c16 = idx & 3;
        const char* s = (const char*)src + (size_t)row * 4096 + kc * 128 + c16 * 16;
        uint32_t off = (uint32_t)(row * 64 + c16 * 16);
        CP_ASYNC16(dst + SW64(off), s);
    }
}
__device__ __forceinline__ void load_B(const __half* src, uint32_t dst,
                                       int kc, int tid) {
    #pragma unroll
    for (int it = 0; it < 4; it++) {
        int idx = it * 128 + tid;
        int row = idx >> 3, c16 = idx & 7;
        const char* s = (const char*)src + (size_t)row * 4096 + kc * 128 + c16 * 16;
        uint32_t off = (uint32_t)(row * 128 + c16 * 16);
        CP_ASYNC16(dst + SW128(off), s);
    }
}

__global__ __launch_bounds__(128, 4) void gram_mma_kernel() {
    extern __shared__ __align__(1024) uint8_t smem[];
    uint32_t sb = smem_u32(smem);
    __shared__ float s_di[128], s_dj[64];

    int tid = threadIdx.x;
    int wid = tid >> 5, lane = tid & 31;
    int bb = blockIdx.y;
    int u = blockIdx.x;

    bool single = (u < 5);
    int r, tj;
    if (single) { r = u; tj = 2 * u; }
    else {
        int p = u - 5; r = 0;
        while (p >= 9 - 2 * r) { p -= 9 - 2 * r; r++; }
        tj = 2 * r + 1 + p;
    }
    int gi0 = 128 * r;           // A strip start (64 rows if single, 128 if pair)
    int gj0 = 64 * tj;
    bool diagb = (!single) && (tj == 2 * r + 1);   // bottom half is diagonal block

    const __half* pA = g_hl + (size_t)(bb * DD + gi0) * 2048;
    const __half* pB = g_hl + (size_t)(bb * DD + gj0) * 2048;

    int a_row = lane & 15;
    int a_kb  = (lane >> 4) * 16;
    int b_row = ((lane >> 4) << 3) + (lane & 7);
    int b_kb  = ((lane >> 3) & 1) * 16;
    int qr = lane >> 2, qc = lane & 3;
    float* stage = reinterpret_cast<float*>(smem);
    float* dcb = g_dcov + (size_t)bb * DD * DD;

    if (!single) {
        // ================= pair path: 128x64, warp w -> rows [32w,32w+32) ===
        float acc[2][8][4];
        #pragma unroll
        for (int i = 0; i < 2; i++)
            #pragma unroll
            for (int j = 0; j < 8; j++)
                #pragma unroll
                for (int k = 0; k < 4; k++) acc[i][j][k] = 0.f;

        load_A(pA, sb, 0, tid, 128);
        load_B(pB, sb + 8192, 0, tid);
        CP_COMMIT();

        for (int kc = 0; kc < NCH; kc++) {
            uint32_t cur = sb + (uint32_t)(kc & 1) * STAGE_BYTES;
            CP_WAIT0();
            __syncthreads();
            if (kc + 1 < NCH) {
                uint32_t nxt = sb + (uint32_t)((kc + 1) & 1) * STAGE_BYTES;
                load_A(pA, nxt, kc + 1, tid, 128);
                load_B(pB, nxt + 8192, kc + 1, tid);
                CP_COMMIT();
            }
            uint32_t Ab = cur, Bb = cur + 8192;
            #pragma unroll
            for (int ks = 0; ks < 2; ks++) {
                uint32_t ah[2][4];
                #pragma unroll
                for (int mt = 0; mt < 2; mt++) {
                    uint32_t off = (uint32_t)((wid * 32 + mt * 16 + a_row) * 64 + ks * 32 + a_kb);
                    LDSM4(ah[mt], Ab + SW64(off));
                }
                #pragma unroll
                for (int nh = 0; nh < 2; nh++) {
                    uint32_t bh[2][4], bl[2][4];
                    #pragma unroll
                    for (int n2 = 0; n2 < 2; n2++) {
                        uint32_t off = (uint32_t)((nh * 32 + n2 * 16 + b_row) * 128 + ks * 32 + b_kb);
                        LDSM4(bh[n2], Bb + SW128(off));
                        LDSM4(bl[n2], Bb + SW128(off + 64));
                    }
                    #pragma unroll
                    for (int mt = 0; mt < 2; mt++)
                        #pragma unroll
                        for (int nt = 0; nt < 4; nt++) {
                            int n2 = nt >> 1, hb = (nt & 1) * 2;
                            MMA_F16(acc[mt][nh * 4 + nt], ah[mt], bh[n2][hb], bh[n2][hb + 1]);
                        }
                    #pragma unroll
                    for (int mt = 0; mt < 2; mt++)
                        #pragma unroll
                        for (int nt = 0; nt < 4; nt++) {
                            int n2 = nt >> 1, hb = (nt & 1) * 2;
                            MMA_F16(acc[mt][nh * 4 + nt], ah[mt], bl[n2][hb], bl[n2][hb + 1]);
                        }
                }
            }
        }

        // ---- epilogue: two 64-row halves through stage[64][68] ----
        s_di[tid] = g_diag[bb * DD + gi0 + tid];
        if (tid < 64) s_dj[tid] = g_diag[bb * DD + gj0 + tid];
        __syncthreads();

        #pragma unroll
        for (int h = 0; h < 2; h++) {
            if ((wid >> 1) == h) {
                int wl = wid & 1;
                #pragma unroll
                for (int mt = 0; mt < 2; mt++) {
                    int rl = wl * 32 + mt * 16 + qr;      // local row in half
                    float di0 = s_di[h * 64 + rl], di1 = s_di[h * 64 + rl + 8];
                    #pragma unroll
                    for (int nt = 0; nt < 8; nt++) {
                        int c0 = nt * 8 + qc * 2;
                        float dj0 = s_dj[c0], dj1 = s_dj[c0 + 1];
                        float* c = acc[mt][nt];
                        stage[rl * 68 + c0]           = sqrtf(fmaf(TEMPR, fmaxf(di0 + dj0 - 2.f * c[0], 0.f), EPSV));
                        stage[rl * 68 + c0 + 1]       = sqrtf(fmaf(TEMPR, fmaxf(di0 + dj1 - 2.f * c[1], 0.f), EPSV));
                        stage[(rl + 8) * 68 + c0]     = sqrtf(fmaf(TEMPR, fmaxf(di1 + dj0 - 2.f * c[2], 0.f), EPSV));
                        stage[(rl + 8) * 68 + c0 + 1] = sqrtf(fmaf(TEMPR, fmaxf(di1 + dj1 - 2.f * c[3], 0.f), EPSV));
                    }
                }
            }
            __syncthreads();
            // dcov store: 64 rows x 64 cols
            #pragma unroll
            for (int it = 0; it < 32; it++) {
                int idx = it * 128 + tid;
                int rr = idx >> 6, cc = idx & 63;
                dcb[(size_t)(gi0 + h * 64 + rr) * DD + gj0 + cc] = stage[rr * 68 + cc];
            }
            // row partials -> slot [tj]
            #pragma unroll
            for (int rr = 0; rr < 16; rr++) {
                int rw = wid * 16 + rr;
                float s = stage[rw * 68 + lane] + stage[rw * 68 + lane + 32];
                #pragma unroll
                for (int o = 16; o > 0; o >>= 1) s += __shfl_down_sync(0xffffffffu, s, o);
                if (lane == 0)
                    g_rspart[((size_t)bb * NBL + tj) * DD + gi0 + h * 64 + rw] = s;
            }
            // mirror col sums -> slot [2r + h], skip if this half is diagonal
            if (!(h == 1 && diagb) && tid < 64) {
                float s = 0.f;
                #pragma unroll 8
                for (int rr = 0; rr < 64; rr++) s += stage[rr * 68 + tid];
                g_rspart[((size_t)bb * NBL + (2 * r + h)) * DD + gj0 + tid] = s;
            }
            __syncthreads();
        }
    } else {
        // ================= single diag path: 64x64 (R16 code) ===============
        int wr = wid >> 1, wc = wid & 1;
        float acc[2][4][4];
        #pragma unroll
        for (int i = 0; i < 2; i++)
            #pragma unroll
            for (int j = 0; j < 4; j++)
                #pragma unroll
                for (int k = 0; k < 4; k++) acc[i][j][k] = 0.f;

        load_A(pA, sb, 0, tid, 64);
        load_B(pB, sb + 8192, 0, tid);
        CP_COMMIT();

        for (int kc = 0; kc < NCH; kc++) {
            uint32_t cur = sb + (uint32_t)(kc & 1) * STAGE_BYTES;
            CP_WAIT0();
            __syncthreads();
            if (kc + 1 < NCH) {
                uint32_t nxt = sb + (uint32_t)((kc + 1) & 1) * STAGE_BYTES;
                load_A(pA, nxt, kc + 1, tid, 64);
                load_B(pB, nxt + 8192, kc + 1, tid);
                CP_COMMIT();
            }
            uint32_t Ab = cur, Bb = cur + 8192;
            #pragma unroll
            for (int ks = 0; ks < 2; ks++) {
                uint32_t bh[2][4], bl[2][4], ah[2][4];
                #pragma unroll
                for (int n2 = 0; n2 < 2; n2++) {
                    uint32_t off = (uint32_t)((wc * 32 + n2 * 16 + b_row) * 128 + ks * 32 + b_kb);
                    LDSM4(bh[n2], Bb + SW128(off));
                    LDSM4(bl[n2], Bb + SW128(off + 64));
                }
                #pragma unroll
                for (int mt = 0; mt < 2; mt++) {
                    uint32_t off = (uint32_t)((wr * 32 + mt * 16 + a_row) * 64 + ks * 32 + a_kb);
                    LDSM4(ah[mt], Ab + SW64(off));
                }
                #pragma unroll
                for (int mt = 0; mt < 2; mt++)
                    #pragma unroll
                    for (int nt = 0; nt < 4; nt++) {
                        int n2 = nt >> 1, hb = (nt & 1) * 2;
                        MMA_F16(acc[mt][nt], ah[mt], bh[n2][hb], bh[n2][hb + 1]);
                    }
                #pragma unroll
                for (int mt = 0; mt < 2; mt++)
                    #pragma unroll
                    for (int nt = 0; nt < 4; nt++) {
                        int n2 = nt >> 1, hb = (nt & 1) * 2;
                        MMA_F16(acc[mt][nt], ah[mt], bl[n2][hb], bl[n2][hb + 1]);
                    }
            }
        }

        if (tid < 64) {
            s_di[tid] = g_diag[bb * DD + gi0 + tid];
            s_dj[tid] = g_diag[bb * DD + gj0 + tid];
        }
        __syncthreads();

        #pragma unroll
        for (int mt = 0; mt < 2; mt++) {
            int r0 = wr * 32 + mt * 16 + qr;
            float di0 = s_di[r0], di1 = s_di[r0 + 8];
            #pragma unroll
            for (int nt = 0; nt < 4; nt++) {
                int c0 = wc * 32 + nt * 8 + qc * 2;
                float dj0 = s_dj[c0], dj1 = s_dj[c0 + 1];
                float* c = acc[mt][nt];
                stage[r0 * 68 + c0]           = sqrtf(fmaf(TEMPR, fmaxf(di0 + dj0 - 2.f * c[0], 0.f), EPSV));
                stage[r0 * 68 + c0 + 1]       = sqrtf(fmaf(TEMPR, fmaxf(di0 + dj1 - 2.f * c[1], 0.f), EPSV));
                stage[(r0 + 8) * 68 + c0]     = sqrtf(fmaf(TEMPR, fmaxf(di1 + dj0 - 2.f * c[2], 0.f), EPSV));
                stage[(r0 + 8) * 68 + c0 + 1] = sqrtf(fmaf(TEMPR, fmaxf(di1 + dj1 - 2.f * c[3], 0.f), EPSV));
            }
        }
        __syncthreads();
        #pragma unroll
        for (int it = 0; it < 32; it++) {
            int idx = it * 128 + tid;
            int rr = idx >> 6, cc = idx & 63;
            dcb[(size_t)(gi0 + rr) * DD + gj0 + cc] = stage[rr * 68 + cc];
        }
        #pragma unroll
        for (int rr = 0; rr < 16; rr++) {
            int rw = wid * 16 + rr;
            float s = stage[rw * 68 + lane] + stage[rw * 68 + lane + 32];
            #pragma unroll
            for (int o = 16; o > 0; o >>= 1) s += __shfl_down_sync(0xffffffffu, s, o);
            if (lane == 0) g_rspart[((size_t)bb * NBL + tj) * DD + gi0 + rw] = s;
        }
        // no mirror for diagonal tile
    }
}

// ---------------------------------------------------------------------------
// Kernel 3: combine partials -> rowsum/D + tot/D^2 (deterministic)
// ---------------------------------------------------------------------------
__global__ void combine_kernel() {
    int b = blockIdx.x;
    __shared__ float sh[256];
    const float inv_d = 1.f / DD;
    float loc = 0.f;
    for (int i = threadIdx.x; i < DD; i += 256) {
        float s = 0.f;
        #pragma unroll
        for (int t = 0; t < NBL; t++) s += g_rspart[((size_t)b * NBL + t) * DD + i];
        g_rowsum[b * DD + i] = s * inv_d;
        loc += s;
    }
    sh[threadIdx.x] = loc;
    __syncthreads();
    #pragma unroll
    for (int o = 128; o > 0; o >>= 1) {
        if (threadIdx.x < o) sh[threadIdx.x] += sh[threadIdx.x + o];
        __syncthreads();
    }
    if (threadIdx.x == 0) g_tot[b] = sh[0] * (inv_d * inv_d);
}

// ---------------------------------------------------------------------------
// Kernel 4: centering + triu gather; flat mapping over the concatenated
// (p, 639-p) row pair (641 elements).
// ---------------------------------------------------------------------------
__global__ void out_kernel(float* __restrict__ out) {
    int p = blockIdx.x;     // 0..319
    int b = blockIdx.y;
    int i0 = p, i1 = DD - 1 - p;
    int len0 = DD - i0;
    float tot = g_tot[b];
    const float* rs = g_rowsum + b * DD;
    float s0 = tot - rs[i0];
    float s1 = tot - rs[i1];
    const float* d0 = g_dcov + ((size_t)b * DD + i0) * DD;
    const float* d1 = g_dcov + ((size_t)b * DD + i1) * DD;
    size_t base0 = (size_t)b * TRI + (size_t)i0 * DD - ((size_t)i0 * (i0 - 1)) / 2 - i0;
    size_t base1 = (size_t)b * TRI + (size_t)i1 * DD - ((size_t)i1 * (i1 - 1)) / 2 - i1;
    #pragma unroll 3
    for (int t = threadIdx.x; t < DD + 1; t += 256) {
        bool r0 = (t < len0);
        int j = r0 ? (i0 + t) : (i1 + (t - len0));
        const float* dp = r0 ? d0 : d1;
        size_t bs = r0 ? base0 : base1;
        float si = r0 ? s0 : s1;
        out[bs + j] = dp[j] - rs[j] + si;
    }
}

// ---------------------------------------------------------------------------
extern "C" void kernel_launch(void* const* d_in, const int* in_sizes, int n_in,
                              void* d_out, int out_size) {
    const float* x = (const float*)d_in[0];
    float* out = (float*)d_out;

    cudaFuncSetAttribute(gram_mma_kernel,
                         cudaFuncAttributeMaxDynamicSharedMemorySize, SMEM_BYTES);

    conv_diag_kernel<<<(BB * DD) / 8, 256>>>(x);
    gram_mma_kernel<<<dim3(NU, BB), 128, SMEM_BYTES>>>();
    combine_kernel<<<BB, 256>>>();
    out_kernel<<<dim3(DD / 2, BB), 256>>>(out);
}